// round 15
// baseline (speedup 1.0000x reference)
#include <cuda_runtime.h>
#include <cuda_bf16.h>
#include <math.h>

#define LSEQ 4096
#define NTOK 8192

// ---------------- float scratch offsets ----------------
#define OFF_QL     ((size_t)0)            // 8192 x 3200 fused qkv+beta+id lin
#define OFF_Q      ((size_t)26214400)
#define OFF_K      ((size_t)34603008)
#define OFF_V      ((size_t)42991616)
#define OFF_U      ((size_t)51380224)
#define OFF_W      ((size_t)59768832)
#define OFF_DELTA  ((size_t)68157440)
#define OFF_FS     ((size_t)76546048)
#define OFF_FL     ((size_t)84934656)
#define OFF_LOGITS ((size_t)93323264)     // 8192 x 12
#define OFF_ATTN   ((size_t)93421568)     // 1024 x 1024
#define OFF_BETA   ((size_t)94470144)
#define OFF_SID    ((size_t)94502912)
#define OFF_P      ((size_t)94535680)
#define BUF_TOTAL  ((size_t)94633984)

__device__ float g_buf[BUF_TOTAL];

// ---------------- bf16 plane offsets (ushort units) ----------------
#define BOFF_X_HI     ((size_t)0)
#define BOFF_X_LO     ((size_t)8388608)
#define BOFF_OM_HI    ((size_t)16777216)
#define BOFF_OM_LO    ((size_t)25165824)
#define BOFF_ST_HI    ((size_t)33554432)   // 8192 x 64 stats
#define BOFF_ST_LO    ((size_t)34078720)
#define BOFF_WQKV_HI  ((size_t)34603008)   // 1024 x 3200
#define BOFF_WQKV_LO  ((size_t)37879808)
#define BOFF_WO_HI    ((size_t)41156608)
#define BOFF_WO_LO    ((size_t)42205184)
#define BOFF_W1_HI    ((size_t)43253760)   // 1088 x 2048
#define BOFF_W1_LO    ((size_t)45481984)
#define BBUF_TOTAL    ((size_t)47710208)

__device__ unsigned short g_bf[BBUF_TOTAL];

__device__ __forceinline__ float sigm(float x){ return 1.0f/(1.0f+expf(-x)); }

__device__ __forceinline__ unsigned short f2bf(float f){
    __nv_bfloat16 h = __float2bfloat16(f);
    return *(unsigned short*)&h;
}
__device__ __forceinline__ float bf2f(unsigned short u){
    __nv_bfloat16 h = *(__nv_bfloat16*)&u;
    return __bfloat162float(h);
}

__device__ __forceinline__ float blockReduceSum(float val, float* red) {
    int lane = threadIdx.x & 31, w = threadIdx.x >> 5;
    #pragma unroll
    for (int o=16;o;o>>=1) val += __shfl_xor_sync(0xffffffffu, val, o);
    if (lane==0) red[w]=val;
    __syncthreads();
    if (w==0) {
        float v2 = (lane<8)? red[lane] : 0.f;
        #pragma unroll
        for (int o=4;o;o>>=1) v2 += __shfl_xor_sync(0xffffffffu, v2, o);
        if (lane==0) red[0]=v2;
    }
    __syncthreads();
    float r = red[0];
    __syncthreads();
    return r;
}

#define LDSM_X4(R0,R1,R2,R3,ADDR) \
    asm volatile("ldmatrix.sync.aligned.m8n8.x4.shared.b16 {%0,%1,%2,%3}, [%4];" \
        : "=r"(R0),"=r"(R1),"=r"(R2),"=r"(R3) : "r"(ADDR))
#define LDSM_X4T(R0,R1,R2,R3,ADDR) \
    asm volatile("ldmatrix.sync.aligned.m8n8.x4.trans.shared.b16 {%0,%1,%2,%3}, [%4];" \
        : "=r"(R0),"=r"(R1),"=r"(R2),"=r"(R3) : "r"(ADDR))
#define MMA_BF16(C,A0,A1,A2,A3,B0,B1) \
    asm volatile("mma.sync.aligned.m16n8k16.row.col.f32.bf16.bf16.f32 " \
        "{%0,%1,%2,%3},{%4,%5,%6,%7},{%8,%9},{%0,%1,%2,%3};" \
        : "+f"(C[0]),"+f"(C[1]),"+f"(C[2]),"+f"(C[3]) \
        : "r"(A0),"r"(A1),"r"(A2),"r"(A3),"r"(B0),"r"(B1))
#define CP16(DST,SRC) \
    asm volatile("cp.async.cg.shared.global [%0], [%1], 16;\n" :: "r"(DST), "l"(SRC))

// GEMM pipeline layout constants — 3-stage ring
#define AL_OFFB  (128*40*2)
#define B_OFFB   (2*128*40*2)
#define BL_OFFB  (32*136*2)
#define STAGE_B  (2*128*40*2 + 2*32*136*2)   // 37888 bytes
#define SMEM_GEMM (3*STAGE_B)                // 113664 bytes

// ---------------- zero kernel ----------------
__global__ void __launch_bounds__(256) zero_kernel(float* dst, int n4)
{
    int idx = blockIdx.x*256 + threadIdx.x;
    if (idx < n4) *(float4*)(dst + (size_t)idx*4) = make_float4(0.f,0.f,0.f,0.f);
}

// ---------------- fp32 -> bf16 hi/lo split (8 elems/thread) ----------------
__global__ void __launch_bounds__(256) f2bf_split_kernel(
    const float* __restrict__ src, unsigned short* __restrict__ hi,
    unsigned short* __restrict__ lo, int n8)
{
    int idx = blockIdx.x*256 + threadIdx.x;
    if (idx >= n8) return;
    const float4* s = (const float4*)(src) + (size_t)idx*2;
    float4 v0 = s[0], v1 = s[1];
    float f[8] = {v0.x,v0.y,v0.z,v0.w,v1.x,v1.y,v1.z,v1.w};
    unsigned hh[4], ll[4];
    #pragma unroll
    for (int i=0;i<4;i++){
        unsigned short h0 = f2bf(f[i*2]), h1 = f2bf(f[i*2+1]);
        unsigned short l0 = f2bf(f[i*2]-bf2f(h0)), l1 = f2bf(f[i*2+1]-bf2f(h1));
        hh[i] = (unsigned)h0 | ((unsigned)h1<<16);
        ll[i] = (unsigned)l0 | ((unsigned)l1<<16);
    }
    *(uint4*)(hi + (size_t)idx*8) = make_uint4(hh[0],hh[1],hh[2],hh[3]);
    *(uint4*)(lo + (size_t)idx*8) = make_uint4(ll[0],ll[1],ll[2],ll[3]);
}

// ------- pack Wq|Wk|Wv|Wb|Wid|0pad -> [1024][3200] bf16 hi/lo --------------
__global__ void __launch_bounds__(256) f2bf_pack_qkv_kernel(
    const float* __restrict__ Wq, const float* __restrict__ Wk,
    const float* __restrict__ Wv, const float* __restrict__ Wb,
    const float* __restrict__ Wid,
    unsigned short* __restrict__ hi, unsigned short* __restrict__ lo)
{
    int idx = blockIdx.x*256 + threadIdx.x;
    if (idx >= 1024*3200/8) return;
    int e0 = idx*8;
    int row = e0 / 3200;
    int col = e0 % 3200;
    float f[8];
    if (col < 3072) {
        int s = col >> 10;
        const float* src = (s==0)? Wq : (s==1)? Wk : Wv;
        const float4* sp = (const float4*)(src + (size_t)row*1024 + (col & 1023));
        float4 a = sp[0], b = sp[1];
        f[0]=a.x; f[1]=a.y; f[2]=a.z; f[3]=a.w; f[4]=b.x; f[5]=b.y; f[6]=b.z; f[7]=b.w;
    } else if (col == 3072) {
        #pragma unroll
        for (int i=0;i<4;i++){ f[i] = Wb[(size_t)row*4+i]; f[4+i] = Wid[(size_t)row*4+i]; }
    } else {
        #pragma unroll
        for (int i=0;i<8;i++) f[i] = 0.f;
    }
    unsigned hh[4], ll[4];
    #pragma unroll
    for (int i=0;i<4;i++){
        unsigned short h0 = f2bf(f[i*2]), h1 = f2bf(f[i*2+1]);
        unsigned short l0 = f2bf(f[i*2]-bf2f(h0)), l1 = f2bf(f[i*2+1]-bf2f(h1));
        hh[i] = (unsigned)h0 | ((unsigned)h1<<16);
        ll[i] = (unsigned)l0 | ((unsigned)l1<<16);
    }
    *(uint4*)(hi + (size_t)idx*8) = make_uint4(hh[0],hh[1],hh[2],hh[3]);
    *(uint4*)(lo + (size_t)idx*8) = make_uint4(ll[0],ll[1],ll[2],ll[3]);
}

// ---------------- Wr1 [1048][2048] -> padded [1088][2048] bf16 split -------
__global__ void __launch_bounds__(256) f2bf_split_pad_kernel(
    const float* __restrict__ src, unsigned short* __restrict__ hi,
    unsigned short* __restrict__ lo)
{
    int idx = blockIdx.x*256 + threadIdx.x;
    if (idx >= 1088*256) return;
    int row = (idx*8) >> 11;
    unsigned hh[4]={0,0,0,0}, ll[4]={0,0,0,0};
    if (row < 1048) {
        const float4* s = (const float4*)(src) + (size_t)idx*2;
        float4 v0 = s[0], v1 = s[1];
        float f[8] = {v0.x,v0.y,v0.z,v0.w,v1.x,v1.y,v1.z,v1.w};
        #pragma unroll
        for (int i=0;i<4;i++){
            unsigned short h0 = f2bf(f[i*2]), h1 = f2bf(f[i*2+1]);
            unsigned short l0 = f2bf(f[i*2]-bf2f(h0)), l1 = f2bf(f[i*2+1]-bf2f(h1));
            hh[i] = (unsigned)h0 | ((unsigned)h1<<16);
            ll[i] = (unsigned)l0 | ((unsigned)l1<<16);
        }
    }
    *(uint4*)(hi + (size_t)idx*8) = make_uint4(hh[0],hh[1],hh[2],hh[3]);
    *(uint4*)(lo + (size_t)idx*8) = make_uint4(ll[0],ll[1],ll[2],ll[3]);
}

// -------- tensor-core GEMM, cp.async 3-stage pipeline (no epilogue) --------
__global__ void __launch_bounds__(256,2) tgemm_kernel(
    const unsigned short* __restrict__ Ahi, const unsigned short* __restrict__ Alo,
    const unsigned short* __restrict__ Bhi, const unsigned short* __restrict__ Blo,
    float* __restrict__ C, int M, int N, int K)
{
    extern __shared__ unsigned short sm[];
    const int tid  = threadIdx.x;
    const int lane = tid & 31;
    const int warp = tid >> 5;
    const int warp_m = warp & 3;
    const int warp_n = warp >> 2;
    const int brow = blockIdx.y * 128;
    const int bcol = blockIdx.x * 128;

    float c[2][8][4];
    #pragma unroll
    for (int i=0;i<2;i++)
        #pragma unroll
        for (int j=0;j<8;j++)
            #pragma unroll
            for (int t=0;t<4;t++) c[i][j][t]=0.f;

    const unsigned sb = (unsigned)__cvta_generic_to_shared(sm);
    const int ar = tid >> 1;
    const int ac = (tid & 1) * 16;
    const int br = tid >> 3;
    const int bc = (tid & 7) * 16;

    const unsigned short* Ahg = Ahi + (size_t)(brow + ar)*K + ac;
    const unsigned short* Alg = Alo + (size_t)(brow + ar)*K + ac;
    const unsigned short* Bhg = Bhi + (size_t)br*N + bcol + bc;
    const unsigned short* Blg = Blo + (size_t)br*N + bcol + bc;

    const unsigned a_dst = sb + (unsigned)(ar*40 + ac)*2u;
    const unsigned b_dst = sb + B_OFFB + (unsigned)(br*136 + bc)*2u;

    #define ISSUE_STAGE(KT, BUF) do {                                   \
        unsigned a0 = a_dst + (BUF)*STAGE_B;                             \
        CP16(a0,            Ahg + (KT));                                 \
        CP16(a0 + 16u,      Ahg + (KT) + 8);                             \
        CP16(a0 + AL_OFFB,       Alg + (KT));                            \
        CP16(a0 + AL_OFFB + 16u, Alg + (KT) + 8);                        \
        unsigned b0 = b_dst + (BUF)*STAGE_B;                             \
        const unsigned short* bhp = Bhg + (size_t)(KT)*N;                \
        const unsigned short* blp = Blg + (size_t)(KT)*N;                \
        CP16(b0,            bhp);                                        \
        CP16(b0 + 16u,      bhp + 8);                                    \
        CP16(b0 + BL_OFFB,       blp);                                   \
        CP16(b0 + BL_OFFB + 16u, blp + 8);                               \
        asm volatile("cp.async.commit_group;\n" ::);                     \
    } while(0)

    const int T = K >> 5;
    ISSUE_STAGE(0, 0);
    ISSUE_STAGE(32, 1);

    int buf = 0;
    for (int t = 0; t < T; t++) {
        if (t + 1 < T) {
            asm volatile("cp.async.wait_group 1;\n" ::);
        } else {
            asm volatile("cp.async.wait_group 0;\n" ::);
        }
        __syncthreads();
        if (t + 2 < T) {
            int nb = buf + 2; if (nb >= 3) nb -= 3;
            ISSUE_STAGE((t+2)*32, nb);
        }

        const unsigned s0 = sb + (unsigned)buf*STAGE_B;
        #pragma unroll
        for (int ks = 0; ks < 2; ks++) {
            unsigned ah[2][4], al[2][4];
            #pragma unroll
            for (int mt = 0; mt < 2; mt++) {
                int ar2 = warp_m*32 + mt*16 + (lane & 15);
                int ac2 = ((lane >> 4) << 3) + ks*16;
                unsigned off = s0 + (unsigned)(ar2*40 + ac2)*2u;
                LDSM_X4(ah[mt][0],ah[mt][1],ah[mt][2],ah[mt][3], off);
                LDSM_X4(al[mt][0],al[mt][1],al[mt][2],al[mt][3], off + AL_OFFB);
            }
            #pragma unroll
            for (int np = 0; np < 4; np++) {
                unsigned bh[4], bl[4];
                int bk = (lane & 7) + (((lane >> 3) & 1) << 3) + ks*16;
                int bn = warp_n*64 + np*16 + ((lane >> 4) << 3);
                unsigned off = s0 + B_OFFB + (unsigned)(bk*136 + bn)*2u;
                LDSM_X4T(bh[0],bh[1],bh[2],bh[3], off);
                LDSM_X4T(bl[0],bl[1],bl[2],bl[3], off + BL_OFFB);
                #pragma unroll
                for (int mt = 0; mt < 2; mt++) {
                    #pragma unroll
                    for (int jj = 0; jj < 2; jj++) {
                        int j = np*2 + jj, o = jj*2;
                        MMA_BF16(c[mt][j], ah[mt][0],ah[mt][1],ah[mt][2],ah[mt][3],
                                 bh[o], bh[o+1]);
                        MMA_BF16(c[mt][j], ah[mt][0],ah[mt][1],ah[mt][2],ah[mt][3],
                                 bl[o], bl[o+1]);
                        MMA_BF16(c[mt][j], al[mt][0],al[mt][1],al[mt][2],al[mt][3],
                                 bh[o], bh[o+1]);
                    }
                }
            }
        }
        if (++buf >= 3) buf = 0;
    }
    #undef ISSUE_STAGE

    #pragma unroll
    for (int mt = 0; mt < 2; mt++) {
        int r0 = brow + warp_m*32 + mt*16 + (lane >> 2);
        #pragma unroll
        for (int j = 0; j < 8; j++) {
            int col = bcol + warp_n*64 + j*8 + (lane & 3)*2;
            *(float2*)&C[(size_t)r0*N + col]     = make_float2(c[mt][j][0], c[mt][j][1]);
            *(float2*)&C[(size_t)(r0+8)*N + col] = make_float2(c[mt][j][2], c[mt][j][3]);
        }
    }
}

// --------- Wr1 GEMM fused with gelu + router logits (atomicAdd), 3-stage ---
__global__ void __launch_bounds__(256,2) tgemm_router_kernel(
    const unsigned short* __restrict__ Axhi, const unsigned short* __restrict__ Axlo,
    const unsigned short* __restrict__ Sthi, const unsigned short* __restrict__ Stlo,
    const unsigned short* __restrict__ Bhi, const unsigned short* __restrict__ Blo,
    const float* __restrict__ bias, const float* __restrict__ Wr2,
    float* __restrict__ logits)
{
    extern __shared__ unsigned short sm[];
    const int tid  = threadIdx.x;
    const int lane = tid & 31;
    const int warp = tid >> 5;
    const int warp_m = warp & 3;
    const int warp_n = warp >> 2;
    const int brow = blockIdx.y * 128;
    const int bcol = blockIdx.x * 128;
    const int N = 2048;

    float c[2][8][4];
    #pragma unroll
    for (int i=0;i<2;i++)
        #pragma unroll
        for (int j=0;j<8;j++)
            #pragma unroll
            for (int t=0;t<4;t++) c[i][j][t]=0.f;

    const unsigned sb = (unsigned)__cvta_generic_to_shared(sm);
    const int ar = tid >> 1;
    const int ac = (tid & 1) * 16;
    const int br = tid >> 3;
    const int bc = (tid & 7) * 16;

    const unsigned short* Bhg = Bhi + (size_t)br*N + bcol + bc;
    const unsigned short* Blg = Blo + (size_t)br*N + bcol + bc;

    const unsigned a_dst = sb + (unsigned)(ar*40 + ac)*2u;
    const unsigned b_dst = sb + B_OFFB + (unsigned)(br*136 + bc)*2u;

    #define TCR_ISSUE(KT, BUF) do {                                          \
        unsigned a0 = a_dst + (BUF)*STAGE_B;                                  \
        const unsigned short* ah_src; const unsigned short* al_src;           \
        if ((KT) < 1024) {                                                    \
            ah_src = Axhi + (size_t)(brow+ar)*1024 + (KT) + ac;               \
            al_src = Axlo + (size_t)(brow+ar)*1024 + (KT) + ac;               \
        } else {                                                              \
            ah_src = Sthi + (size_t)(brow+ar)*64 + ((KT)-1024) + ac;          \
            al_src = Stlo + (size_t)(brow+ar)*64 + ((KT)-1024) + ac;          \
        }                                                                     \
        CP16(a0,            ah_src);                                          \
        CP16(a0 + 16u,      ah_src + 8);                                      \
        CP16(a0 + AL_OFFB,       al_src);                                     \
        CP16(a0 + AL_OFFB + 16u, al_src + 8);                                 \
        unsigned b0 = b_dst + (BUF)*STAGE_B;                                  \
        const unsigned short* bhp = Bhg + (size_t)(KT)*N;                     \
        const unsigned short* blp = Blg + (size_t)(KT)*N;                     \
        CP16(b0,            bhp);                                             \
        CP16(b0 + 16u,      bhp + 8);                                         \
        CP16(b0 + BL_OFFB,       blp);                                        \
        CP16(b0 + BL_OFFB + 16u, blp + 8);                                    \
        asm volatile("cp.async.commit_group;\n" ::);                          \
    } while(0)

    const int T = 34;     // K = 1088
    TCR_ISSUE(0, 0);
    TCR_ISSUE(32, 1);

    int buf = 0;
    for (int t = 0; t < T; t++) {
        if (t + 1 < T) {
            asm volatile("cp.async.wait_group 1;\n" ::);
        } else {
            asm volatile("cp.async.wait_group 0;\n" ::);
        }
        __syncthreads();
        if (t + 2 < T) {
            int nb = buf + 2; if (nb >= 3) nb -= 3;
            TCR_ISSUE((t+2)*32, nb);
        }

        const unsigned s0 = sb + (unsigned)buf*STAGE_B;
        #pragma unroll
        for (int ks = 0; ks < 2; ks++) {
            unsigned ah[2][4], al[2][4];
            #pragma unroll
            for (int mt = 0; mt < 2; mt++) {
                int ar2 = warp_m*32 + mt*16 + (lane & 15);
                int ac2 = ((lane >> 4) << 3) + ks*16;
                unsigned off = s0 + (unsigned)(ar2*40 + ac2)*2u;
                LDSM_X4(ah[mt][0],ah[mt][1],ah[mt][2],ah[mt][3], off);
                LDSM_X4(al[mt][0],al[mt][1],al[mt][2],al[mt][3], off + AL_OFFB);
            }
            #pragma unroll
            for (int np = 0; np < 4; np++) {
                unsigned bh[4], bl[4];
                int bk = (lane & 7) + (((lane >> 3) & 1) << 3) + ks*16;
                int bn = warp_n*64 + np*16 + ((lane >> 4) << 3);
                unsigned off = s0 + B_OFFB + (unsigned)(bk*136 + bn)*2u;
                LDSM_X4T(bh[0],bh[1],bh[2],bh[3], off);
                LDSM_X4T(bl[0],bl[1],bl[2],bl[3], off + BL_OFFB);
                #pragma unroll
                for (int mt = 0; mt < 2; mt++) {
                    #pragma unroll
                    for (int jj = 0; jj < 2; jj++) {
                        int j = np*2 + jj, o = jj*2;
                        MMA_BF16(c[mt][j], ah[mt][0],ah[mt][1],ah[mt][2],ah[mt][3],
                                 bh[o], bh[o+1]);
                        MMA_BF16(c[mt][j], ah[mt][0],ah[mt][1],ah[mt][2],ah[mt][3],
                                 bl[o], bl[o+1]);
                        MMA_BF16(c[mt][j], al[mt][0],al[mt][1],al[mt][2],al[mt][3],
                                 bh[o], bh[o+1]);
                    }
                }
            }
        }
        if (++buf >= 3) buf = 0;
    }
    #undef TCR_ISSUE

    __syncthreads();
    // ---- fused epilogue: bias + exact gelu + router partial logits ----
    float* w2s = (float*)sm;      // 128 cols x 12 outs = 1536 floats
    for (int i = tid; i < 1536; i += 256)
        w2s[i] = Wr2[(size_t)(bcol + i/12)*12 + (i%12)];
    __syncthreads();

    #pragma unroll
    for (int mt = 0; mt < 2; mt++) {
        #pragma unroll
        for (int rr = 0; rr < 2; rr++) {
            int row = brow + warp_m*32 + mt*16 + (lane >> 2) + rr*8;
            float lsum[12];
            #pragma unroll
            for (int o2=0;o2<12;o2++) lsum[o2]=0.f;
            #pragma unroll
            for (int j = 0; j < 8; j++) {
                int cl = warp_n*64 + j*8 + (lane & 3)*2;
                float v0 = c[mt][j][rr*2+0] + bias[bcol+cl];
                float v1 = c[mt][j][rr*2+1] + bias[bcol+cl+1];
                v0 = 0.5f*v0*(1.0f+erff(v0*0.70710678118654752f));
                v1 = 0.5f*v1*(1.0f+erff(v1*0.70710678118654752f));
                #pragma unroll
                for (int o2=0;o2<12;o2++)
                    lsum[o2] += v0*w2s[cl*12+o2] + v1*w2s[(cl+1)*12+o2];
            }
            #pragma unroll
            for (int o2=0;o2<12;o2++){
                lsum[o2] += __shfl_xor_sync(0xffffffffu, lsum[o2], 1);
                lsum[o2] += __shfl_xor_sync(0xffffffffu, lsum[o2], 2);
            }
            if ((lane & 3) == 0) {
                #pragma unroll
                for (int o2=0;o2<12;o2++)
                    atomicAdd(&logits[(size_t)row*12 + o2], lsum[o2]);
            }
        }
    }
}

// ---------------- beta + id-gate from qkvlin cols 3072..3079 ----------------
__global__ void __launch_bounds__(256) beta_sid_kernel(
    const float* __restrict__ qkvlin, const float* __restrict__ bid,
    float* __restrict__ beta, float* __restrict__ sid)
{
    int idx = blockIdx.x*256 + threadIdx.x;
    if (idx >= NTOK*4) return;
    int n = idx >> 2, h = idx & 3;
    const float* row = qkvlin + (size_t)n*3200;
    beta[idx] = sigm(row[3072 + h]);
    sid[idx]  = sigm(row[3076 + h] + bid[h]);
}

// ---------------- fused causal depthwise conv (k=4) + silu, 3 streams -------
__global__ void __launch_bounds__(256) conv_silu_kernel(
    const float* __restrict__ in, const float* __restrict__ cq,
    const float* __restrict__ ck, const float* __restrict__ cv,
    float* __restrict__ qb, float* __restrict__ kb, float* __restrict__ vb)
{
    long long gidx = (long long)blockIdx.x*256 + threadIdx.x;
    int s = (int)(gidx >> 23);
    int idx = (int)(gidx & ((1<<23)-1));
    int c = idx & 1023;
    int n = idx >> 10;
    int l = n & (LSEQ-1);
    const float* cw = (s==0)? cq : (s==1)? ck : cv;
    float* out = (s==0)? qb : (s==1)? kb : vb;
    float4 wv = *(const float4*)(cw + (size_t)c*4);
    float wj[4] = {wv.x, wv.y, wv.z, wv.w};
    float acc = 0.f;
    #pragma unroll
    for (int j=0;j<4;j++){
        int t = l - 3 + j;
        if (t >= 0) acc += in[(size_t)(n-3+j)*3200 + s*1024 + c] * wj[j];
    }
    out[idx] = acc / (1.0f + expf(-acc));
}

// ---------------- per-chunk prep: l2norm, T, u, w, attn ----------------
__global__ void __launch_bounds__(256) chunk_prep_kernel(
    float* __restrict__ q, float* __restrict__ k, const float* __restrict__ v,
    const float* __restrict__ beta, float* __restrict__ u, float* __restrict__ w,
    float* __restrict__ attn)
{
    extern __shared__ float sh[];
    float* qs = sh;
    float* ks = qs + 32*260;
    float* vs = ks + 32*260;
    float* T  = vs + 32*260;
    float* bet = T + 32*33;
    int ci = blockIdx.x;
    int c = ci & 127;
    int h = (ci >> 7) & 3;
    int b = ci >> 9;
    int tid = threadIdx.x;
    size_t base = ((size_t)(b*LSEQ + c*32))*1024 + (size_t)h*256;
    for (int i=tid; i<2048; i+=256) {
        int r = i>>6; int d4 = (i&63)<<2;
        size_t off = base + (size_t)r*1024 + d4;
        *(float4*)&qs[r*260+d4] = *(const float4*)(q + off);
        *(float4*)&ks[r*260+d4] = *(const float4*)(k + off);
        *(float4*)&vs[r*260+d4] = *(const float4*)(v + off);
    }
    if (tid < 32) bet[tid] = beta[(size_t)(b*LSEQ + c*32 + tid)*4 + h];
    __syncthreads();
    {
        int wi = tid>>5, lane = tid&31;
        for (int r = wi*4; r < wi*4+4; r++) {
            float sq=0.f, sk2=0.f;
            for (int dd=lane; dd<256; dd+=32){
                float a=qs[r*260+dd]; sq+=a*a;
                float bb=ks[r*260+dd]; sk2+=bb*bb;
            }
            #pragma unroll
            for (int o=16;o;o>>=1){
                sq+=__shfl_xor_sync(0xffffffffu,sq,o);
                sk2+=__shfl_xor_sync(0xffffffffu,sk2,o);
            }
            float rq = rsqrtf(sq+1e-6f), rk = rsqrtf(sk2+1e-6f);
            for (int dd=lane; dd<256; dd+=32){ qs[r*260+dd]*=rq; ks[r*260+dd]*=rk; }
        }
    }
    __syncthreads();
    size_t abase = (size_t)ci*1024;
    for (int pp=tid; pp<1024; pp+=256) {
        int i = pp>>5, j = pp&31;
        float dkk=0.f, dqq=0.f;
        for (int dd=0; dd<256; dd++){
            float kj = ks[j*260+dd];
            dkk += ks[i*260+dd]*kj;
            dqq += qs[i*260+dd]*kj;
        }
        T[i*33+j] = (j<i)? (-bet[i]*dkk) : 0.f;
        attn[abase+pp] = (j<=i)? dqq : 0.f;
    }
    __syncthreads();
    if (tid<32) {
        int lane = tid;
        for (int i=1;i<32;i++){
            float rowv = T[i*33+lane];
            float add = 0.f;
            for (int j=0;j<i;j++) add += __shfl_sync(0xffffffffu, rowv, j)*T[j*33+lane];
            T[i*33+lane] = rowv + add;
            __syncwarp();
        }
        T[lane*33+lane] += 1.0f;
    }
    __syncthreads();
    for (int pp=tid; pp<8192; pp+=256){
        int r = pp>>8, dd = pp&255;
        float su=0.f, sw=0.f;
        #pragma unroll
        for (int j=0;j<32;j++){
            float tj = T[r*33+j]*bet[j];
            su += tj*vs[j*260+dd];
            sw += tj*ks[j*260+dd];
        }
        size_t off = base + (size_t)r*1024 + dd;
        u[off]=su; w[off]=sw;
        q[off]=qs[r*260+dd]; k[off]=ks[r*260+dd];
    }
}

// ---------------- sequential chunk scan, dv-sliced (16 slices of 16) -------
__global__ void __launch_bounds__(512) scan_kernel(
    const float* __restrict__ q, const float* __restrict__ k,
    const float* __restrict__ u, const float* __restrict__ w,
    const float* __restrict__ attn, float* __restrict__ outp)
{
    extern __shared__ float sh[];
    float* S  = sh;
    float* qs = S + 4096;
    float* ks = qs + 8320;
    float* ws = ks + 8320;
    float* as = ws + 8320;
    float* u2 = as + 1024;
    int bid = blockIdx.x;
    int sl = bid & 15;
    int bh = bid >> 4;
    int h = bh & 3, b = bh >> 2;
    int tid = threadIdx.x;
    for (int i=tid;i<4096;i+=512) S[i]=0.f;
    const int iRow = tid >> 4;
    const int q1 = tid & 15;
    const int dd0 = tid >> 2;
    const int c4 = (tid & 3) * 4;
    size_t abh = (size_t)bh * 128 * 1024;
    for (int c=0;c<128;c++){
        size_t base = ((size_t)(b*LSEQ + c*32))*1024 + (size_t)h*256;
        __syncthreads();
        for (int i=tid;i<2048;i+=512){
            int r=i>>6; int d4=(i&63)<<2;
            size_t off = base + (size_t)r*1024 + d4;
            *(float4*)&qs[r*260+d4] = *(const float4*)(q+off);
            *(float4*)&ks[r*260+d4] = *(const float4*)(k+off);
            *(float4*)&ws[r*260+d4] = *(const float4*)(w+off);
        }
        if (tid < 256)
            *(float4*)&as[tid*4] = *(const float4*)(attn + abh + (size_t)c*1024 + tid*4);
        __syncthreads();
        float au = u[base + (size_t)iRow*1024 + sl*16 + q1];
        float ao = 0.f;
        #pragma unroll 8
        for (int dd=0; dd<256; dd++){
            float Sv = S[dd*16+q1];
            au -= ws[iRow*260+dd]*Sv;
            ao += qs[iRow*260+dd]*Sv;
        }
        u2[iRow*16+q1] = au;
        __syncthreads();
        #pragma unroll
        for (int j=0;j<32;j++) ao += as[iRow*32+j]*u2[j*16+q1];
        outp[base + (size_t)iRow*1024 + sl*16 + q1] = ao;
        #pragma unroll
        for (int s2=0; s2<2; s2++){
            int dd = dd0 + s2*128;
            float4 Sv = *(float4*)&S[dd*16+c4];
            #pragma unroll 8
            for (int j=0;j<32;j++){
                float kv = ks[j*260+dd];
                float4 uv = *(float4*)&u2[j*16+c4];
                Sv.x += kv*uv.x; Sv.y += kv*uv.y; Sv.z += kv*uv.z; Sv.w += kv*uv.w;
            }
            *(float4*)&S[dd*16+c4] = Sv;
        }
    }
}

// ---------------- FIR + stats (smem-tiled, bf16 stats plane out) -----------
__global__ void __launch_bounds__(256) fir_stats_kernel(
    const float* __restrict__ v, const float* __restrict__ dlt,
    const float* __restrict__ firS, const float* __restrict__ firL,
    float* __restrict__ fs, float* __restrict__ fl,
    unsigned short* __restrict__ sthi, unsigned short* __restrict__ stlo)
{
    extern __shared__ float vsm[];
    __shared__ float red[8][6];
    const int h  = blockIdx.y;
    const int t0 = blockIdx.x * 32;
    const int l0 = t0 & (LSEQ-1);
    const int tid = threadIdx.x;
    const int d = tid;
    const int cidx = h*256 + d;
    const int lane = tid & 31, wrp = tid >> 5;

    if (h == 0 && tid < 32) {
        size_t dst = (size_t)(t0+tid)*64 + 24;
        #pragma unroll
        for (int j=0;j<5;j++){
            *(uint4*)(sthi + dst + j*8) = make_uint4(0,0,0,0);
            *(uint4*)(stlo + dst + j*8) = make_uint4(0,0,0,0);
        }
    }

    for (int i = tid; i < 62*64; i += 256) {
        int r = i >> 6; int c4 = (i & 63) << 2;
        float4 val = make_float4(0.f,0.f,0.f,0.f);
        if (l0 - 30 + r >= 0)
            val = *(const float4*)(v + (size_t)(t0-30+r)*1024 + h*256 + c4);
        *(float4*)&vsm[r*256 + c4] = val;
    }
    __syncthreads();

    float fS[3], fL[31];
    #pragma unroll
    for (int j=0;j<3;j++)  fS[j] = firS[(size_t)cidx*3+j];
    #pragma unroll
    for (int j=0;j<31;j++) fL[j] = firL[(size_t)cidx*31+j];

    for (int tt = 0; tt < 32; tt++) {
        int row = tt + 30;
        int n = t0 + tt;
        float accS = 0.f;
        #pragma unroll
        for (int j=0;j<3;j++) accS += vsm[(row-2+j)*256 + d]*fS[j];
        float accL = 0.f;
        #pragma unroll
        for (int j=0;j<31;j++) accL += vsm[(row-30+j)*256 + d]*fL[j];
        float dv = dlt[(size_t)n*1024 + cidx];
        fs[(size_t)n*1024 + cidx] = accS;
        fl[(size_t)n*1024 + cidx] = accL;

        float vals[6] = {accS, accS*accS, accL, accL*accL, dv, dv*dv};
        #pragma unroll
        for (int k2=0;k2<6;k2++){
            float s = vals[k2];
            #pragma unroll
            for (int o=16;o;o>>=1) s += __shfl_xor_sync(0xffffffffu, s, o);
            if (lane==0) red[wrp][k2] = s;
        }
        __syncthreads();
        if (tid == 0) {
            float s[6];
            #pragma unroll
            for (int k2=0;k2<6;k2++){
                float a = 0.f;
                #pragma unroll
                for (int ww=0;ww<8;ww++) a += red[ww][k2];
                s[k2] = a;
            }
            float m1 = s[0]*(1.f/256.f), m3 = s[2]*(1.f/256.f), m5 = s[4]*(1.f/256.f);
            float o[6];
            o[0]=m1;
            o[1]=sqrtf(fmaxf(s[1]*(1.f/256.f)-m1*m1,0.f));
            o[2]=m3;
            o[3]=sqrtf(fmaxf(s[3]*(1.f/256.f)-m3*m3,0.f));
            o[4]=m5;
            o[5]=sqrtf(fmaxf(s[5]*(1.f/256.f)-m5*m5,0.f));
            size_t rb = (size_t)n*64 + h;
            #pragma unroll
            for (int k2=0;k2<6;k2++){
                unsigned short hh = f2bf(o[k2]);
                sthi[rb + k2*4] = hh;
                stlo[rb + k2*4] = f2bf(o[k2]-bf2f(hh));
            }
        }
        __syncthreads();
    }
}

// ---------------- softmax over router logits ----------------
__global__ void __launch_bounds__(256) softmax_router_kernel(
    const float* __restrict__ logits, const float* __restrict__ br2,
    const float* __restrict__ ltg, float* __restrict__ p)
{
    int n = blockIdx.x*256 + threadIdx.x;
    if (n >= NTOK) return;
    float lg[12];
    #pragma unroll
    for (int i=0;i<12;i++) lg[i] = logits[(size_t)n*12+i] + br2[i];
    #pragma unroll
    for (int h=0;h<4;h++){
        float tau = expf(ltg[h>>1]);
        float a = lg[h*3+0]/tau, bq = lg[h*3+1]/tau, cq = lg[h*3+2]/tau;
        float m = fmaxf(a, fmaxf(bq,cq));
        float ea=expf(a-m), eb=expf(bq-m), ec=expf(cq-m);
        float inv = 1.f/(ea+eb+ec);
        p[(size_t)n*12 + h*3+0] = ea*inv*0.925f + 0.025f;
        p[(size_t)n*12 + h*3+1] = eb*inv*0.925f + 0.025f;
        p[(size_t)n*12 + h*3+2] = ec*inv*0.925f + 0.025f;
    }
}

// ---------------- gated mix + id + RMS norm -> bf16 hi/lo -------------------
__global__ void __launch_bounds__(256) mix_norm_kernel(
    const float* __restrict__ p, const float* __restrict__ fs,
    const float* __restrict__ fl, const float* __restrict__ dlt,
    const float* __restrict__ v, const float* __restrict__ sid,
    const float* __restrict__ alpha_id, const float* __restrict__ onw,
    unsigned short* __restrict__ omhi, unsigned short* __restrict__ omlo)
{
    int n = blockIdx.x;
    int d = threadIdx.x;
    __shared__ float red[8];
    for (int h=0;h<4;h++){
        size_t idx = (size_t)n*1024 + h*256 + d;
        float p0 = p[(size_t)n*12+h*3+0];
        float p1 = p[(size_t)n*12+h*3+1];
        float p2 = p[(size_t)n*12+h*3+2];
        float ids = 0.06f + sigm(alpha_id[h]) * sid[(size_t)n*4+h];
        float o = p0*fs[idx] + p1*fl[idx] + p2*dlt[idx] + ids*v[idx];
        float ss = blockReduceSum(o*o, red);
        float r = rsqrtf(ss*(1.f/256.f) + 1e-5f);
        float val = o*r*onw[d];
        unsigned short hh = f2bf(val);
        omhi[idx] = hh;
        omlo[idx] = f2bf(val - bf2f(hh));
    }
}

extern "C" void kernel_launch(void* const* d_in, const int* in_sizes, int n_in,
                              void* d_out, int out_size) {
    const float* x    = (const float*)d_in[0];
    const float* Wq   = (const float*)d_in[1];
    const float* Wk   = (const float*)d_in[2];
    const float* Wv   = (const float*)d_in[3];
    const float* Wb   = (const float*)d_in[4];
    const float* cq   = (const float*)d_in[5];
    const float* ck   = (const float*)d_in[6];
    const float* cv   = (const float*)d_in[7];
    const float* firS = (const float*)d_in[8];
    const float* firL = (const float*)d_in[9];
    const float* aid  = (const float*)d_in[10];
    const float* Wid  = (const float*)d_in[11];
    const float* bid  = (const float*)d_in[12];
    const float* Wr1  = (const float*)d_in[13];
    const float* br1  = (const float*)d_in[14];
    const float* Wr2  = (const float*)d_in[15];
    const float* br2  = (const float*)d_in[16];
    const float* ltg  = (const float*)d_in[17];
    const float* onw  = (const float*)d_in[19];
    const float* Wo   = (const float*)d_in[20];
    float* out = (float*)d_out;

    void* bufv = nullptr;
    cudaGetSymbolAddress(&bufv, g_buf);
    float* buf = (float*)bufv;
    void* bbufv = nullptr;
    cudaGetSymbolAddress(&bbufv, g_bf);
    unsigned short* bbuf = (unsigned short*)bbufv;

    float* qkvlin = buf + OFF_QL;
    float* qb   = buf + OFF_Q;
    float* kb   = buf + OFF_K;
    float* vb   = buf + OFF_V;
    float* ub   = buf + OFF_U;
    float* wb   = buf + OFF_W;
    float* dlt  = buf + OFF_DELTA;
    float* fsb  = buf + OFF_FS;
    float* flb  = buf + OFF_FL;
    float* lgts = buf + OFF_LOGITS;
    float* attn = buf + OFF_ATTN;
    float* beta = buf + OFF_BETA;
    float* sidb = buf + OFF_SID;
    float* pb   = buf + OFF_P;

    unsigned short* xhi  = bbuf + BOFF_X_HI;
    unsigned short* xlo  = bbuf + BOFF_X_LO;
    unsigned short* omhi = bbuf + BOFF_OM_HI;
    unsigned short* omlo = bbuf + BOFF_OM_LO;
    unsigned short* sthi = bbuf + BOFF_ST_HI;
    unsigned short* stlo = bbuf + BOFF_ST_LO;
    unsigned short* wqkvhi = bbuf + BOFF_WQKV_HI;
    unsigned short* wqkvlo = bbuf + BOFF_WQKV_LO;
    unsigned short* wohi = bbuf + BOFF_WO_HI;
    unsigned short* wolo = bbuf + BOFF_WO_LO;
    unsigned short* w1hi = bbuf + BOFF_W1_HI;
    unsigned short* w1lo = bbuf + BOFF_W1_LO;

    int smem_prep = (3*32*260 + 32*33 + 32) * 4;
    int smem_scan = (4096 + 3*8320 + 1024 + 512) * 4;
    int smem_fir  = 62*256*4;
    cudaFuncSetAttribute(chunk_prep_kernel, cudaFuncAttributeMaxDynamicSharedMemorySize, smem_prep);
    cudaFuncSetAttribute(scan_kernel, cudaFuncAttributeMaxDynamicSharedMemorySize, smem_scan);
    cudaFuncSetAttribute(fir_stats_kernel, cudaFuncAttributeMaxDynamicSharedMemorySize, smem_fir);
    cudaFuncSetAttribute(tgemm_kernel, cudaFuncAttributeMaxDynamicSharedMemorySize, SMEM_GEMM);
    cudaFuncSetAttribute(tgemm_router_kernel, cudaFuncAttributeMaxDynamicSharedMemorySize, SMEM_GEMM);

    // ---- init + conversions ----
    zero_kernel<<<96, 256>>>(lgts, NTOK*12/4);
    f2bf_split_kernel<<<4096, 256>>>(x, xhi, xlo, 8192*1024/8);
    f2bf_pack_qkv_kernel<<<1600, 256>>>(Wq, Wk, Wv, Wb, Wid, wqkvhi, wqkvlo);
    f2bf_split_kernel<<<512, 256>>>(Wo, wohi, wolo, 1024*1024/8);
    f2bf_split_pad_kernel<<<1088, 256>>>(Wr1, w1hi, w1lo);

    dim3 blk(256);
    dim3 gqkv(25, 64);
    tgemm_kernel<<<gqkv, blk, SMEM_GEMM>>>(xhi, xlo, wqkvhi, wqkvlo, qkvlin, NTOK, 3200, 1024);
    beta_sid_kernel<<<128, 256>>>(qkvlin, bid, beta, sidb);
    conv_silu_kernel<<<3*NTOK*4, 256>>>(qkvlin, cq, ck, cv, qb, kb, vb);
    chunk_prep_kernel<<<1024, 256, smem_prep>>>(qb, kb, vb, beta, ub, wb, attn);
    scan_kernel<<<128, 512, smem_scan>>>(qb, kb, ub, wb, attn, dlt);
    dim3 gfir(NTOK/32, 4);
    fir_stats_kernel<<<gfir, 256, smem_fir>>>(vb, dlt, firS, firL, fsb, flb, sthi, stlo);
    dim3 g2(16, 64);
    tgemm_router_kernel<<<g2, blk, SMEM_GEMM>>>(xhi, xlo, sthi, stlo, w1hi, w1lo, br1, Wr2, lgts);
    softmax_router_kernel<<<32, 256>>>(lgts, br2, ltg, pb);
    mix_norm_kernel<<<NTOK, 256>>>(pb, fsb, flb, dlt, vb, sidb, aid, onw, omhi, omlo);
    dim3 g1(8, 64);
    tgemm_kernel<<<g1, blk, SMEM_GEMM>>>(omhi, omlo, wohi, wolo, out, NTOK, 1024, 1024);
}

// round 16
// speedup vs baseline: 1.0010x; 1.0010x over previous
#include <cuda_runtime.h>
#include <cuda_bf16.h>
#include <math.h>

#define LSEQ 4096
#define NTOK 8192

// ---------------- float scratch offsets ----------------
#define OFF_QL     ((size_t)0)            // 8192 x 3200 fused qkv+beta+id lin
#define OFF_Q      ((size_t)26214400)
#define OFF_K      ((size_t)34603008)
#define OFF_V      ((size_t)42991616)
#define OFF_U      ((size_t)51380224)
#define OFF_W      ((size_t)59768832)
#define OFF_DELTA  ((size_t)68157440)
#define OFF_FS     ((size_t)76546048)
#define OFF_FL     ((size_t)84934656)
#define OFF_LOGITS ((size_t)93323264)     // 8192 x 12
#define OFF_ATTN   ((size_t)93421568)     // 1024 x 1024
#define OFF_BETA   ((size_t)94470144)
#define OFF_SID    ((size_t)94502912)
#define OFF_P      ((size_t)94535680)
#define BUF_TOTAL  ((size_t)94633984)

__device__ float g_buf[BUF_TOTAL];

// ---------------- bf16 plane offsets (ushort units) ----------------
#define BOFF_X_HI     ((size_t)0)
#define BOFF_X_LO     ((size_t)8388608)
#define BOFF_OM_HI    ((size_t)16777216)
#define BOFF_OM_LO    ((size_t)25165824)
#define BOFF_ST_HI    ((size_t)33554432)   // 8192 x 64 stats
#define BOFF_ST_LO    ((size_t)34078720)
#define BOFF_WQKV_HI  ((size_t)34603008)   // 1024 x 3200
#define BOFF_WQKV_LO  ((size_t)37879808)
#define BOFF_WO_HI    ((size_t)41156608)
#define BOFF_WO_LO    ((size_t)42205184)
#define BOFF_W1_HI    ((size_t)43253760)   // 1088 x 2048
#define BOFF_W1_LO    ((size_t)45481984)
#define BBUF_TOTAL    ((size_t)47710208)

__device__ unsigned short g_bf[BBUF_TOTAL];

__device__ __forceinline__ float sigm(float x){ return 1.0f/(1.0f+expf(-x)); }

__device__ __forceinline__ unsigned short f2bf(float f){
    __nv_bfloat16 h = __float2bfloat16(f);
    return *(unsigned short*)&h;
}
__device__ __forceinline__ float bf2f(unsigned short u){
    __nv_bfloat16 h = *(__nv_bfloat16*)&u;
    return __bfloat162float(h);
}

__device__ __forceinline__ float blockReduceSum(float val, float* red) {
    int lane = threadIdx.x & 31, w = threadIdx.x >> 5;
    #pragma unroll
    for (int o=16;o;o>>=1) val += __shfl_xor_sync(0xffffffffu, val, o);
    if (lane==0) red[w]=val;
    __syncthreads();
    if (w==0) {
        float v2 = (lane<8)? red[lane] : 0.f;
        #pragma unroll
        for (int o=4;o;o>>=1) v2 += __shfl_xor_sync(0xffffffffu, v2, o);
        if (lane==0) red[0]=v2;
    }
    __syncthreads();
    float r = red[0];
    __syncthreads();
    return r;
}

#define LDSM_X4(R0,R1,R2,R3,ADDR) \
    asm volatile("ldmatrix.sync.aligned.m8n8.x4.shared.b16 {%0,%1,%2,%3}, [%4];" \
        : "=r"(R0),"=r"(R1),"=r"(R2),"=r"(R3) : "r"(ADDR))
#define LDSM_X4T(R0,R1,R2,R3,ADDR) \
    asm volatile("ldmatrix.sync.aligned.m8n8.x4.trans.shared.b16 {%0,%1,%2,%3}, [%4];" \
        : "=r"(R0),"=r"(R1),"=r"(R2),"=r"(R3) : "r"(ADDR))
#define MMA_BF16(C,A0,A1,A2,A3,B0,B1) \
    asm volatile("mma.sync.aligned.m16n8k16.row.col.f32.bf16.bf16.f32 " \
        "{%0,%1,%2,%3},{%4,%5,%6,%7},{%8,%9},{%0,%1,%2,%3};" \
        : "+f"(C[0]),"+f"(C[1]),"+f"(C[2]),"+f"(C[3]) \
        : "r"(A0),"r"(A1),"r"(A2),"r"(A3),"r"(B0),"r"(B1))
#define CP16(DST,SRC) \
    asm volatile("cp.async.cg.shared.global [%0], [%1], 16;\n" :: "r"(DST), "l"(SRC))

// GEMM pipeline layout constants — 3-stage ring
#define AL_OFFB  (128*40*2)
#define B_OFFB   (2*128*40*2)
#define BL_OFFB  (32*136*2)
#define STAGE_B  (2*128*40*2 + 2*32*136*2)   // 37888 bytes
#define SMEM_GEMM (3*STAGE_B)                // 113664 bytes

// ---------------- zero kernel ----------------
__global__ void __launch_bounds__(256) zero_kernel(float* dst, int n4)
{
    int idx = blockIdx.x*256 + threadIdx.x;
    if (idx < n4) *(float4*)(dst + (size_t)idx*4) = make_float4(0.f,0.f,0.f,0.f);
}

// ---------------- fp32 -> bf16 hi/lo split (8 elems/thread) ----------------
__global__ void __launch_bounds__(256) f2bf_split_kernel(
    const float* __restrict__ src, unsigned short* __restrict__ hi,
    unsigned short* __restrict__ lo, int n8)
{
    int idx = blockIdx.x*256 + threadIdx.x;
    if (idx >= n8) return;
    const float4* s = (const float4*)(src) + (size_t)idx*2;
    float4 v0 = s[0], v1 = s[1];
    float f[8] = {v0.x,v0.y,v0.z,v0.w,v1.x,v1.y,v1.z,v1.w};
    unsigned hh[4], ll[4];
    #pragma unroll
    for (int i=0;i<4;i++){
        unsigned short h0 = f2bf(f[i*2]), h1 = f2bf(f[i*2+1]);
        unsigned short l0 = f2bf(f[i*2]-bf2f(h0)), l1 = f2bf(f[i*2+1]-bf2f(h1));
        hh[i] = (unsigned)h0 | ((unsigned)h1<<16);
        ll[i] = (unsigned)l0 | ((unsigned)l1<<16);
    }
    *(uint4*)(hi + (size_t)idx*8) = make_uint4(hh[0],hh[1],hh[2],hh[3]);
    *(uint4*)(lo + (size_t)idx*8) = make_uint4(ll[0],ll[1],ll[2],ll[3]);
}

// ------- pack Wq|Wk|Wv|Wb|Wid|0pad -> [1024][3200] bf16 hi/lo --------------
__global__ void __launch_bounds__(256) f2bf_pack_qkv_kernel(
    const float* __restrict__ Wq, const float* __restrict__ Wk,
    const float* __restrict__ Wv, const float* __restrict__ Wb,
    const float* __restrict__ Wid,
    unsigned short* __restrict__ hi, unsigned short* __restrict__ lo)
{
    int idx = blockIdx.x*256 + threadIdx.x;
    if (idx >= 1024*3200/8) return;
    int e0 = idx*8;
    int row = e0 / 3200;
    int col = e0 % 3200;
    float f[8];
    if (col < 3072) {
        int s = col >> 10;
        const float* src = (s==0)? Wq : (s==1)? Wk : Wv;
        const float4* sp = (const float4*)(src + (size_t)row*1024 + (col & 1023));
        float4 a = sp[0], b = sp[1];
        f[0]=a.x; f[1]=a.y; f[2]=a.z; f[3]=a.w; f[4]=b.x; f[5]=b.y; f[6]=b.z; f[7]=b.w;
    } else if (col == 3072) {
        #pragma unroll
        for (int i=0;i<4;i++){ f[i] = Wb[(size_t)row*4+i]; f[4+i] = Wid[(size_t)row*4+i]; }
    } else {
        #pragma unroll
        for (int i=0;i<8;i++) f[i] = 0.f;
    }
    unsigned hh[4], ll[4];
    #pragma unroll
    for (int i=0;i<4;i++){
        unsigned short h0 = f2bf(f[i*2]), h1 = f2bf(f[i*2+1]);
        unsigned short l0 = f2bf(f[i*2]-bf2f(h0)), l1 = f2bf(f[i*2+1]-bf2f(h1));
        hh[i] = (unsigned)h0 | ((unsigned)h1<<16);
        ll[i] = (unsigned)l0 | ((unsigned)l1<<16);
    }
    *(uint4*)(hi + (size_t)idx*8) = make_uint4(hh[0],hh[1],hh[2],hh[3]);
    *(uint4*)(lo + (size_t)idx*8) = make_uint4(ll[0],ll[1],ll[2],ll[3]);
}

// ---------------- Wr1 [1048][2048] -> padded [1088][2048] bf16 split -------
__global__ void __launch_bounds__(256) f2bf_split_pad_kernel(
    const float* __restrict__ src, unsigned short* __restrict__ hi,
    unsigned short* __restrict__ lo)
{
    int idx = blockIdx.x*256 + threadIdx.x;
    if (idx >= 1088*256) return;
    int row = (idx*8) >> 11;
    unsigned hh[4]={0,0,0,0}, ll[4]={0,0,0,0};
    if (row < 1048) {
        const float4* s = (const float4*)(src) + (size_t)idx*2;
        float4 v0 = s[0], v1 = s[1];
        float f[8] = {v0.x,v0.y,v0.z,v0.w,v1.x,v1.y,v1.z,v1.w};
        #pragma unroll
        for (int i=0;i<4;i++){
            unsigned short h0 = f2bf(f[i*2]), h1 = f2bf(f[i*2+1]);
            unsigned short l0 = f2bf(f[i*2]-bf2f(h0)), l1 = f2bf(f[i*2+1]-bf2f(h1));
            hh[i] = (unsigned)h0 | ((unsigned)h1<<16);
            ll[i] = (unsigned)l0 | ((unsigned)l1<<16);
        }
    }
    *(uint4*)(hi + (size_t)idx*8) = make_uint4(hh[0],hh[1],hh[2],hh[3]);
    *(uint4*)(lo + (size_t)idx*8) = make_uint4(ll[0],ll[1],ll[2],ll[3]);
}

// -------- tensor-core GEMM, cp.async 3-stage pipeline (no epilogue) --------
__global__ void __launch_bounds__(256,2) tgemm_kernel(
    const unsigned short* __restrict__ Ahi, const unsigned short* __restrict__ Alo,
    const unsigned short* __restrict__ Bhi, const unsigned short* __restrict__ Blo,
    float* __restrict__ C, int M, int N, int K)
{
    extern __shared__ unsigned short sm[];
    const int tid  = threadIdx.x;
    const int lane = tid & 31;
    const int warp = tid >> 5;
    const int warp_m = warp & 3;
    const int warp_n = warp >> 2;
    const int brow = blockIdx.y * 128;
    const int bcol = blockIdx.x * 128;

    float c[2][8][4];
    #pragma unroll
    for (int i=0;i<2;i++)
        #pragma unroll
        for (int j=0;j<8;j++)
            #pragma unroll
            for (int t=0;t<4;t++) c[i][j][t]=0.f;

    const unsigned sb = (unsigned)__cvta_generic_to_shared(sm);
    const int ar = tid >> 1;
    const int ac = (tid & 1) * 16;
    const int br = tid >> 3;
    const int bc = (tid & 7) * 16;

    const unsigned short* Ahg = Ahi + (size_t)(brow + ar)*K + ac;
    const unsigned short* Alg = Alo + (size_t)(brow + ar)*K + ac;
    const unsigned short* Bhg = Bhi + (size_t)br*N + bcol + bc;
    const unsigned short* Blg = Blo + (size_t)br*N + bcol + bc;

    const unsigned a_dst = sb + (unsigned)(ar*40 + ac)*2u;
    const unsigned b_dst = sb + B_OFFB + (unsigned)(br*136 + bc)*2u;

    #define ISSUE_STAGE(KT, BUF) do {                                   \
        unsigned a0 = a_dst + (BUF)*STAGE_B;                             \
        CP16(a0,            Ahg + (KT));                                 \
        CP16(a0 + 16u,      Ahg + (KT) + 8);                             \
        CP16(a0 + AL_OFFB,       Alg + (KT));                            \
        CP16(a0 + AL_OFFB + 16u, Alg + (KT) + 8);                        \
        unsigned b0 = b_dst + (BUF)*STAGE_B;                             \
        const unsigned short* bhp = Bhg + (size_t)(KT)*N;                \
        const unsigned short* blp = Blg + (size_t)(KT)*N;                \
        CP16(b0,            bhp);                                        \
        CP16(b0 + 16u,      bhp + 8);                                    \
        CP16(b0 + BL_OFFB,       blp);                                   \
        CP16(b0 + BL_OFFB + 16u, blp + 8);                               \
        asm volatile("cp.async.commit_group;\n" ::);                     \
    } while(0)

    const int T = K >> 5;
    ISSUE_STAGE(0, 0);
    ISSUE_STAGE(32, 1);

    int buf = 0;
    for (int t = 0; t < T; t++) {
        if (t + 1 < T) {
            asm volatile("cp.async.wait_group 1;\n" ::);
        } else {
            asm volatile("cp.async.wait_group 0;\n" ::);
        }
        __syncthreads();
        if (t + 2 < T) {
            int nb = buf + 2; if (nb >= 3) nb -= 3;
            ISSUE_STAGE((t+2)*32, nb);
        }

        const unsigned s0 = sb + (unsigned)buf*STAGE_B;
        #pragma unroll
        for (int ks = 0; ks < 2; ks++) {
            unsigned ah[2][4], al[2][4];
            #pragma unroll
            for (int mt = 0; mt < 2; mt++) {
                int ar2 = warp_m*32 + mt*16 + (lane & 15);
                int ac2 = ((lane >> 4) << 3) + ks*16;
                unsigned off = s0 + (unsigned)(ar2*40 + ac2)*2u;
                LDSM_X4(ah[mt][0],ah[mt][1],ah[mt][2],ah[mt][3], off);
                LDSM_X4(al[mt][0],al[mt][1],al[mt][2],al[mt][3], off + AL_OFFB);
            }
            #pragma unroll
            for (int np = 0; np < 4; np++) {
                unsigned bh[4], bl[4];
                int bk = (lane & 7) + (((lane >> 3) & 1) << 3) + ks*16;
                int bn = warp_n*64 + np*16 + ((lane >> 4) << 3);
                unsigned off = s0 + B_OFFB + (unsigned)(bk*136 + bn)*2u;
                LDSM_X4T(bh[0],bh[1],bh[2],bh[3], off);
                LDSM_X4T(bl[0],bl[1],bl[2],bl[3], off + BL_OFFB);
                #pragma unroll
                for (int mt = 0; mt < 2; mt++) {
                    #pragma unroll
                    for (int jj = 0; jj < 2; jj++) {
                        int j = np*2 + jj, o = jj*2;
                        MMA_BF16(c[mt][j], ah[mt][0],ah[mt][1],ah[mt][2],ah[mt][3],
                                 bh[o], bh[o+1]);
                        MMA_BF16(c[mt][j], ah[mt][0],ah[mt][1],ah[mt][2],ah[mt][3],
                                 bl[o], bl[o+1]);
                        MMA_BF16(c[mt][j], al[mt][0],al[mt][1],al[mt][2],al[mt][3],
                                 bh[o], bh[o+1]);
                    }
                }
            }
        }
        if (++buf >= 3) buf = 0;
    }
    #undef ISSUE_STAGE

    #pragma unroll
    for (int mt = 0; mt < 2; mt++) {
        int r0 = brow + warp_m*32 + mt*16 + (lane >> 2);
        #pragma unroll
        for (int j = 0; j < 8; j++) {
            int col = bcol + warp_n*64 + j*8 + (lane & 3)*2;
            *(float2*)&C[(size_t)r0*N + col]     = make_float2(c[mt][j][0], c[mt][j][1]);
            *(float2*)&C[(size_t)(r0+8)*N + col] = make_float2(c[mt][j][2], c[mt][j][3]);
        }
    }
}

// --------- Wr1 GEMM fused with gelu + router logits (atomicAdd), 3-stage ---
__global__ void __launch_bounds__(256,2) tgemm_router_kernel(
    const unsigned short* __restrict__ Axhi, const unsigned short* __restrict__ Axlo,
    const unsigned short* __restrict__ Sthi, const unsigned short* __restrict__ Stlo,
    const unsigned short* __restrict__ Bhi, const unsigned short* __restrict__ Blo,
    const float* __restrict__ bias, const float* __restrict__ Wr2,
    float* __restrict__ logits)
{
    extern __shared__ unsigned short sm[];
    const int tid  = threadIdx.x;
    const int lane = tid & 31;
    const int warp = tid >> 5;
    const int warp_m = warp & 3;
    const int warp_n = warp >> 2;
    const int brow = blockIdx.y * 128;
    const int bcol = blockIdx.x * 128;
    const int N = 2048;

    float c[2][8][4];
    #pragma unroll
    for (int i=0;i<2;i++)
        #pragma unroll
        for (int j=0;j<8;j++)
            #pragma unroll
            for (int t=0;t<4;t++) c[i][j][t]=0.f;

    const unsigned sb = (unsigned)__cvta_generic_to_shared(sm);
    const int ar = tid >> 1;
    const int ac = (tid & 1) * 16;
    const int br = tid >> 3;
    const int bc = (tid & 7) * 16;

    const unsigned short* Bhg = Bhi + (size_t)br*N + bcol + bc;
    const unsigned short* Blg = Blo + (size_t)br*N + bcol + bc;

    const unsigned a_dst = sb + (unsigned)(ar*40 + ac)*2u;
    const unsigned b_dst = sb + B_OFFB + (unsigned)(br*136 + bc)*2u;

    #define TCR_ISSUE(KT, BUF) do {                                          \
        unsigned a0 = a_dst + (BUF)*STAGE_B;                                  \
        const unsigned short* ah_src; const unsigned short* al_src;           \
        if ((KT) < 1024) {                                                    \
            ah_src = Axhi + (size_t)(brow+ar)*1024 + (KT) + ac;               \
            al_src = Axlo + (size_t)(brow+ar)*1024 + (KT) + ac;               \
        } else {                                                              \
            ah_src = Sthi + (size_t)(brow+ar)*64 + ((KT)-1024) + ac;          \
            al_src = Stlo + (size_t)(brow+ar)*64 + ((KT)-1024) + ac;          \
        }                                                                     \
        CP16(a0,            ah_src);                                          \
        CP16(a0 + 16u,      ah_src + 8);                                      \
        CP16(a0 + AL_OFFB,       al_src);                                     \
        CP16(a0 + AL_OFFB + 16u, al_src + 8);                                 \
        unsigned b0 = b_dst + (BUF)*STAGE_B;                                  \
        const unsigned short* bhp = Bhg + (size_t)(KT)*N;                     \
        const unsigned short* blp = Blg + (size_t)(KT)*N;                     \
        CP16(b0,            bhp);                                             \
        CP16(b0 + 16u,      bhp + 8);                                         \
        CP16(b0 + BL_OFFB,       blp);                                        \
        CP16(b0 + BL_OFFB + 16u, blp + 8);                                    \
        asm volatile("cp.async.commit_group;\n" ::);                          \
    } while(0)

    const int T = 34;     // K = 1088
    TCR_ISSUE(0, 0);
    TCR_ISSUE(32, 1);

    int buf = 0;
    for (int t = 0; t < T; t++) {
        if (t + 1 < T) {
            asm volatile("cp.async.wait_group 1;\n" ::);
        } else {
            asm volatile("cp.async.wait_group 0;\n" ::);
        }
        __syncthreads();
        if (t + 2 < T) {
            int nb = buf + 2; if (nb >= 3) nb -= 3;
            TCR_ISSUE((t+2)*32, nb);
        }

        const unsigned s0 = sb + (unsigned)buf*STAGE_B;
        #pragma unroll
        for (int ks = 0; ks < 2; ks++) {
            unsigned ah[2][4], al[2][4];
            #pragma unroll
            for (int mt = 0; mt < 2; mt++) {
                int ar2 = warp_m*32 + mt*16 + (lane & 15);
                int ac2 = ((lane >> 4) << 3) + ks*16;
                unsigned off = s0 + (unsigned)(ar2*40 + ac2)*2u;
                LDSM_X4(ah[mt][0],ah[mt][1],ah[mt][2],ah[mt][3], off);
                LDSM_X4(al[mt][0],al[mt][1],al[mt][2],al[mt][3], off + AL_OFFB);
            }
            #pragma unroll
            for (int np = 0; np < 4; np++) {
                unsigned bh[4], bl[4];
                int bk = (lane & 7) + (((lane >> 3) & 1) << 3) + ks*16;
                int bn = warp_n*64 + np*16 + ((lane >> 4) << 3);
                unsigned off = s0 + B_OFFB + (unsigned)(bk*136 + bn)*2u;
                LDSM_X4T(bh[0],bh[1],bh[2],bh[3], off);
                LDSM_X4T(bl[0],bl[1],bl[2],bl[3], off + BL_OFFB);
                #pragma unroll
                for (int mt = 0; mt < 2; mt++) {
                    #pragma unroll
                    for (int jj = 0; jj < 2; jj++) {
                        int j = np*2 + jj, o = jj*2;
                        MMA_BF16(c[mt][j], ah[mt][0],ah[mt][1],ah[mt][2],ah[mt][3],
                                 bh[o], bh[o+1]);
                        MMA_BF16(c[mt][j], ah[mt][0],ah[mt][1],ah[mt][2],ah[mt][3],
                                 bl[o], bl[o+1]);
                        MMA_BF16(c[mt][j], al[mt][0],al[mt][1],al[mt][2],al[mt][3],
                                 bh[o], bh[o+1]);
                    }
                }
            }
        }
        if (++buf >= 3) buf = 0;
    }
    #undef TCR_ISSUE

    __syncthreads();
    // ---- fused epilogue: bias + exact gelu + router partial logits ----
    float* w2s = (float*)sm;      // 128 cols x 12 outs = 1536 floats
    for (int i = tid; i < 1536; i += 256)
        w2s[i] = Wr2[(size_t)(bcol + i/12)*12 + (i%12)];
    __syncthreads();

    #pragma unroll
    for (int mt = 0; mt < 2; mt++) {
        #pragma unroll
        for (int rr = 0; rr < 2; rr++) {
            int row = brow + warp_m*32 + mt*16 + (lane >> 2) + rr*8;
            float lsum[12];
            #pragma unroll
            for (int o2=0;o2<12;o2++) lsum[o2]=0.f;
            #pragma unroll
            for (int j = 0; j < 8; j++) {
                int cl = warp_n*64 + j*8 + (lane & 3)*2;
                float v0 = c[mt][j][rr*2+0] + bias[bcol+cl];
                float v1 = c[mt][j][rr*2+1] + bias[bcol+cl+1];
                v0 = 0.5f*v0*(1.0f+erff(v0*0.70710678118654752f));
                v1 = 0.5f*v1*(1.0f+erff(v1*0.70710678118654752f));
                #pragma unroll
                for (int o2=0;o2<12;o2++)
                    lsum[o2] += v0*w2s[cl*12+o2] + v1*w2s[(cl+1)*12+o2];
            }
            #pragma unroll
            for (int o2=0;o2<12;o2++){
                lsum[o2] += __shfl_xor_sync(0xffffffffu, lsum[o2], 1);
                lsum[o2] += __shfl_xor_sync(0xffffffffu, lsum[o2], 2);
            }
            if ((lane & 3) == 0) {
                #pragma unroll
                for (int o2=0;o2<12;o2++)
                    atomicAdd(&logits[(size_t)row*12 + o2], lsum[o2]);
            }
        }
    }
}

// ---------------- beta + id-gate from qkvlin cols 3072..3079 ----------------
__global__ void __launch_bounds__(256) beta_sid_kernel(
    const float* __restrict__ qkvlin, const float* __restrict__ bid,
    float* __restrict__ beta, float* __restrict__ sid)
{
    int idx = blockIdx.x*256 + threadIdx.x;
    if (idx >= NTOK*4) return;
    int n = idx >> 2, h = idx & 3;
    const float* row = qkvlin + (size_t)n*3200;
    beta[idx] = sigm(row[3072 + h]);
    sid[idx]  = sigm(row[3076 + h] + bid[h]);
}

// ---------------- fused causal depthwise conv (k=4) + silu, 3 streams -------
__global__ void __launch_bounds__(256) conv_silu_kernel(
    const float* __restrict__ in, const float* __restrict__ cq,
    const float* __restrict__ ck, const float* __restrict__ cv,
    float* __restrict__ qb, float* __restrict__ kb, float* __restrict__ vb)
{
    long long gidx = (long long)blockIdx.x*256 + threadIdx.x;
    int s = (int)(gidx >> 23);
    int idx = (int)(gidx & ((1<<23)-1));
    int c = idx & 1023;
    int n = idx >> 10;
    int l = n & (LSEQ-1);
    const float* cw = (s==0)? cq : (s==1)? ck : cv;
    float* out = (s==0)? qb : (s==1)? kb : vb;
    float4 wv = *(const float4*)(cw + (size_t)c*4);
    float wj[4] = {wv.x, wv.y, wv.z, wv.w};
    float acc = 0.f;
    #pragma unroll
    for (int j=0;j<4;j++){
        int t = l - 3 + j;
        if (t >= 0) acc += in[(size_t)(n-3+j)*3200 + s*1024 + c] * wj[j];
    }
    out[idx] = acc / (1.0f + expf(-acc));
}

// ---------------- per-chunk prep: l2norm, T, u, w, attn ----------------
__global__ void __launch_bounds__(256) chunk_prep_kernel(
    float* __restrict__ q, float* __restrict__ k, const float* __restrict__ v,
    const float* __restrict__ beta, float* __restrict__ u, float* __restrict__ w,
    float* __restrict__ attn)
{
    extern __shared__ float sh[];
    float* qs = sh;
    float* ks = qs + 32*260;
    float* vs = ks + 32*260;
    float* T  = vs + 32*260;
    float* bet = T + 32*33;
    int ci = blockIdx.x;
    int c = ci & 127;
    int h = (ci >> 7) & 3;
    int b = ci >> 9;
    int tid = threadIdx.x;
    size_t base = ((size_t)(b*LSEQ + c*32))*1024 + (size_t)h*256;
    for (int i=tid; i<2048; i+=256) {
        int r = i>>6; int d4 = (i&63)<<2;
        size_t off = base + (size_t)r*1024 + d4;
        *(float4*)&qs[r*260+d4] = *(const float4*)(q + off);
        *(float4*)&ks[r*260+d4] = *(const float4*)(k + off);
        *(float4*)&vs[r*260+d4] = *(const float4*)(v + off);
    }
    if (tid < 32) bet[tid] = beta[(size_t)(b*LSEQ + c*32 + tid)*4 + h];
    __syncthreads();
    {
        int wi = tid>>5, lane = tid&31;
        for (int r = wi*4; r < wi*4+4; r++) {
            float sq=0.f, sk2=0.f;
            for (int dd=lane; dd<256; dd+=32){
                float a=qs[r*260+dd]; sq+=a*a;
                float bb=ks[r*260+dd]; sk2+=bb*bb;
            }
            #pragma unroll
            for (int o=16;o;o>>=1){
                sq+=__shfl_xor_sync(0xffffffffu,sq,o);
                sk2+=__shfl_xor_sync(0xffffffffu,sk2,o);
            }
            float rq = rsqrtf(sq+1e-6f), rk = rsqrtf(sk2+1e-6f);
            for (int dd=lane; dd<256; dd+=32){ qs[r*260+dd]*=rq; ks[r*260+dd]*=rk; }
        }
    }
    __syncthreads();
    size_t abase = (size_t)ci*1024;
    for (int pp=tid; pp<1024; pp+=256) {
        int i = pp>>5, j = pp&31;
        float dkk=0.f, dqq=0.f;
        for (int dd=0; dd<256; dd++){
            float kj = ks[j*260+dd];
            dkk += ks[i*260+dd]*kj;
            dqq += qs[i*260+dd]*kj;
        }
        T[i*33+j] = (j<i)? (-bet[i]*dkk) : 0.f;
        attn[abase+pp] = (j<=i)? dqq : 0.f;
    }
    __syncthreads();
    if (tid<32) {
        int lane = tid;
        for (int i=1;i<32;i++){
            float rowv = T[i*33+lane];
            float add = 0.f;
            for (int j=0;j<i;j++) add += __shfl_sync(0xffffffffu, rowv, j)*T[j*33+lane];
            T[i*33+lane] = rowv + add;
            __syncwarp();
        }
        T[lane*33+lane] += 1.0f;
    }
    __syncthreads();
    for (int pp=tid; pp<8192; pp+=256){
        int r = pp>>8, dd = pp&255;
        float su=0.f, sw=0.f;
        #pragma unroll
        for (int j=0;j<32;j++){
            float tj = T[r*33+j]*bet[j];
            su += tj*vs[j*260+dd];
            sw += tj*ks[j*260+dd];
        }
        size_t off = base + (size_t)r*1024 + dd;
        u[off]=su; w[off]=sw;
        q[off]=qs[r*260+dd]; k[off]=ks[r*260+dd];
    }
}

// ---------------- sequential chunk scan, dv-sliced (16 slices of 16) -------
__global__ void __launch_bounds__(512) scan_kernel(
    const float* __restrict__ q, const float* __restrict__ k,
    const float* __restrict__ u, const float* __restrict__ w,
    const float* __restrict__ attn, float* __restrict__ outp)
{
    extern __shared__ float sh[];
    float* S  = sh;
    float* qs = S + 4096;
    float* ks = qs + 8320;
    float* ws = ks + 8320;
    float* as = ws + 8320;
    float* u2 = as + 1024;
    int bid = blockIdx.x;
    int sl = bid & 15;
    int bh = bid >> 4;
    int h = bh & 3, b = bh >> 2;
    int tid = threadIdx.x;
    for (int i=tid;i<4096;i+=512) S[i]=0.f;
    const int iRow = tid >> 4;
    const int q1 = tid & 15;
    const int dd0 = tid >> 2;
    const int c4 = (tid & 3) * 4;
    size_t abh = (size_t)bh * 128 * 1024;
    for (int c=0;c<128;c++){
        size_t base = ((size_t)(b*LSEQ + c*32))*1024 + (size_t)h*256;
        __syncthreads();
        for (int i=tid;i<2048;i+=512){
            int r=i>>6; int d4=(i&63)<<2;
            size_t off = base + (size_t)r*1024 + d4;
            *(float4*)&qs[r*260+d4] = *(const float4*)(q+off);
            *(float4*)&ks[r*260+d4] = *(const float4*)(k+off);
            *(float4*)&ws[r*260+d4] = *(const float4*)(w+off);
        }
        if (tid < 256)
            *(float4*)&as[tid*4] = *(const float4*)(attn + abh + (size_t)c*1024 + tid*4);
        __syncthreads();
        float au = u[base + (size_t)iRow*1024 + sl*16 + q1];
        float ao = 0.f;
        #pragma unroll 8
        for (int dd=0; dd<256; dd++){
            float Sv = S[dd*16+q1];
            au -= ws[iRow*260+dd]*Sv;
            ao += qs[iRow*260+dd]*Sv;
        }
        u2[iRow*16+q1] = au;
        __syncthreads();
        #pragma unroll
        for (int j=0;j<32;j++) ao += as[iRow*32+j]*u2[j*16+q1];
        outp[base + (size_t)iRow*1024 + sl*16 + q1] = ao;
        #pragma unroll
        for (int s2=0; s2<2; s2++){
            int dd = dd0 + s2*128;
            float4 Sv = *(float4*)&S[dd*16+c4];
            #pragma unroll 8
            for (int j=0;j<32;j++){
                float kv = ks[j*260+dd];
                float4 uv = *(float4*)&u2[j*16+c4];
                Sv.x += kv*uv.x; Sv.y += kv*uv.y; Sv.z += kv*uv.z; Sv.w += kv*uv.w;
            }
            *(float4*)&S[dd*16+c4] = Sv;
        }
    }
}

// ---------------- FIR + stats (smem-tiled, bf16 stats plane out) -----------
__global__ void __launch_bounds__(256) fir_stats_kernel(
    const float* __restrict__ v, const float* __restrict__ dlt,
    const float* __restrict__ firS, const float* __restrict__ firL,
    float* __restrict__ fs, float* __restrict__ fl,
    unsigned short* __restrict__ sthi, unsigned short* __restrict__ stlo)
{
    extern __shared__ float vsm[];
    __shared__ float red[8][6];
    const int h  = blockIdx.y;
    const int t0 = blockIdx.x * 32;
    const int l0 = t0 & (LSEQ-1);
    const int tid = threadIdx.x;
    const int d = tid;
    const int cidx = h*256 + d;
    const int lane = tid & 31, wrp = tid >> 5;

    if (h == 0 && tid < 32) {
        size_t dst = (size_t)(t0+tid)*64 + 24;
        #pragma unroll
        for (int j=0;j<5;j++){
            *(uint4*)(sthi + dst + j*8) = make_uint4(0,0,0,0);
            *(uint4*)(stlo + dst + j*8) = make_uint4(0,0,0,0);
        }
    }

    for (int i = tid; i < 62*64; i += 256) {
        int r = i >> 6; int c4 = (i & 63) << 2;
        float4 val = make_float4(0.f,0.f,0.f,0.f);
        if (l0 - 30 + r >= 0)
            val = *(const float4*)(v + (size_t)(t0-30+r)*1024 + h*256 + c4);
        *(float4*)&vsm[r*256 + c4] = val;
    }
    __syncthreads();

    float fS[3], fL[31];
    #pragma unroll
    for (int j=0;j<3;j++)  fS[j] = firS[(size_t)cidx*3+j];
    #pragma unroll
    for (int j=0;j<31;j++) fL[j] = firL[(size_t)cidx*31+j];

    for (int tt = 0; tt < 32; tt++) {
        int row = tt + 30;
        int n = t0 + tt;
        float accS = 0.f;
        #pragma unroll
        for (int j=0;j<3;j++) accS += vsm[(row-2+j)*256 + d]*fS[j];
        float accL = 0.f;
        #pragma unroll
        for (int j=0;j<31;j++) accL += vsm[(row-30+j)*256 + d]*fL[j];
        float dv = dlt[(size_t)n*1024 + cidx];
        fs[(size_t)n*1024 + cidx] = accS;
        fl[(size_t)n*1024 + cidx] = accL;

        float vals[6] = {accS, accS*accS, accL, accL*accL, dv, dv*dv};
        #pragma unroll
        for (int k2=0;k2<6;k2++){
            float s = vals[k2];
            #pragma unroll
            for (int o=16;o;o>>=1) s += __shfl_xor_sync(0xffffffffu, s, o);
            if (lane==0) red[wrp][k2] = s;
        }
        __syncthreads();
        if (tid == 0) {
            float s[6];
            #pragma unroll
            for (int k2=0;k2<6;k2++){
                float a = 0.f;
                #pragma unroll
                for (int ww=0;ww<8;ww++) a += red[ww][k2];
                s[k2] = a;
            }
            float m1 = s[0]*(1.f/256.f), m3 = s[2]*(1.f/256.f), m5 = s[4]*(1.f/256.f);
            float o[6];
            o[0]=m1;
            o[1]=sqrtf(fmaxf(s[1]*(1.f/256.f)-m1*m1,0.f));
            o[2]=m3;
            o[3]=sqrtf(fmaxf(s[3]*(1.f/256.f)-m3*m3,0.f));
            o[4]=m5;
            o[5]=sqrtf(fmaxf(s[5]*(1.f/256.f)-m5*m5,0.f));
            size_t rb = (size_t)n*64 + h;
            #pragma unroll
            for (int k2=0;k2<6;k2++){
                unsigned short hh = f2bf(o[k2]);
                sthi[rb + k2*4] = hh;
                stlo[rb + k2*4] = f2bf(o[k2]-bf2f(hh));
            }
        }
        __syncthreads();
    }
}

// ---------------- softmax over router logits ----------------
__global__ void __launch_bounds__(256) softmax_router_kernel(
    const float* __restrict__ logits, const float* __restrict__ br2,
    const float* __restrict__ ltg, float* __restrict__ p)
{
    int n = blockIdx.x*256 + threadIdx.x;
    if (n >= NTOK) return;
    float lg[12];
    #pragma unroll
    for (int i=0;i<12;i++) lg[i] = logits[(size_t)n*12+i] + br2[i];
    #pragma unroll
    for (int h=0;h<4;h++){
        float tau = expf(ltg[h>>1]);
        float a = lg[h*3+0]/tau, bq = lg[h*3+1]/tau, cq = lg[h*3+2]/tau;
        float m = fmaxf(a, fmaxf(bq,cq));
        float ea=expf(a-m), eb=expf(bq-m), ec=expf(cq-m);
        float inv = 1.f/(ea+eb+ec);
        p[(size_t)n*12 + h*3+0] = ea*inv*0.925f + 0.025f;
        p[(size_t)n*12 + h*3+1] = eb*inv*0.925f + 0.025f;
        p[(size_t)n*12 + h*3+2] = ec*inv*0.925f + 0.025f;
    }
}

// ---------------- gated mix + id + RMS norm -> bf16 hi/lo -------------------
__global__ void __launch_bounds__(256) mix_norm_kernel(
    const float* __restrict__ p, const float* __restrict__ fs,
    const float* __restrict__ fl, const float* __restrict__ dlt,
    const float* __restrict__ v, const float* __restrict__ sid,
    const float* __restrict__ alpha_id, const float* __restrict__ onw,
    unsigned short* __restrict__ omhi, unsigned short* __restrict__ omlo)
{
    int n = blockIdx.x;
    int d = threadIdx.x;
    __shared__ float red[8];
    for (int h=0;h<4;h++){
        size_t idx = (size_t)n*1024 + h*256 + d;
        float p0 = p[(size_t)n*12+h*3+0];
        float p1 = p[(size_t)n*12+h*3+1];
        float p2 = p[(size_t)n*12+h*3+2];
        float ids = 0.06f + sigm(alpha_id[h]) * sid[(size_t)n*4+h];
        float o = p0*fs[idx] + p1*fl[idx] + p2*dlt[idx] + ids*v[idx];
        float ss = blockReduceSum(o*o, red);
        float r = rsqrtf(ss*(1.f/256.f) + 1e-5f);
        float val = o*r*onw[d];
        unsigned short hh = f2bf(val);
        omhi[idx] = hh;
        omlo[idx] = f2bf(val - bf2f(hh));
    }
}

extern "C" void kernel_launch(void* const* d_in, const int* in_sizes, int n_in,
                              void* d_out, int out_size) {
    const float* x    = (const float*)d_in[0];
    const float* Wq   = (const float*)d_in[1];
    const float* Wk   = (const float*)d_in[2];
    const float* Wv   = (const float*)d_in[3];
    const float* Wb   = (const float*)d_in[4];
    const float* cq   = (const float*)d_in[5];
    const float* ck   = (const float*)d_in[6];
    const float* cv   = (const float*)d_in[7];
    const float* firS = (const float*)d_in[8];
    const float* firL = (const float*)d_in[9];
    const float* aid  = (const float*)d_in[10];
    const float* Wid  = (const float*)d_in[11];
    const float* bid  = (const float*)d_in[12];
    const float* Wr1  = (const float*)d_in[13];
    const float* br1  = (const float*)d_in[14];
    const float* Wr2  = (const float*)d_in[15];
    const float* br2  = (const float*)d_in[16];
    const float* ltg  = (const float*)d_in[17];
    const float* onw  = (const float*)d_in[19];
    const float* Wo   = (const float*)d_in[20];
    float* out = (float*)d_out;

    void* bufv = nullptr;
    cudaGetSymbolAddress(&bufv, g_buf);
    float* buf = (float*)bufv;
    void* bbufv = nullptr;
    cudaGetSymbolAddress(&bbufv, g_bf);
    unsigned short* bbuf = (unsigned short*)bbufv;

    float* qkvlin = buf + OFF_QL;
    float* qb   = buf + OFF_Q;
    float* kb   = buf + OFF_K;
    float* vb   = buf + OFF_V;
    float* ub   = buf + OFF_U;
    float* wb   = buf + OFF_W;
    float* dlt  = buf + OFF_DELTA;
    float* fsb  = buf + OFF_FS;
    float* flb  = buf + OFF_FL;
    float* lgts = buf + OFF_LOGITS;
    float* attn = buf + OFF_ATTN;
    float* beta = buf + OFF_BETA;
    float* sidb = buf + OFF_SID;
    float* pb   = buf + OFF_P;

    unsigned short* xhi  = bbuf + BOFF_X_HI;
    unsigned short* xlo  = bbuf + BOFF_X_LO;
    unsigned short* omhi = bbuf + BOFF_OM_HI;
    unsigned short* omlo = bbuf + BOFF_OM_LO;
    unsigned short* sthi = bbuf + BOFF_ST_HI;
    unsigned short* stlo = bbuf + BOFF_ST_LO;
    unsigned short* wqkvhi = bbuf + BOFF_WQKV_HI;
    unsigned short* wqkvlo = bbuf + BOFF_WQKV_LO;
    unsigned short* wohi = bbuf + BOFF_WO_HI;
    unsigned short* wolo = bbuf + BOFF_WO_LO;
    unsigned short* w1hi = bbuf + BOFF_W1_HI;
    unsigned short* w1lo = bbuf + BOFF_W1_LO;

    int smem_prep = (3*32*260 + 32*33 + 32) * 4;
    int smem_scan = (4096 + 3*8320 + 1024 + 512) * 4;
    int smem_fir  = 62*256*4;
    cudaFuncSetAttribute(chunk_prep_kernel, cudaFuncAttributeMaxDynamicSharedMemorySize, smem_prep);
    cudaFuncSetAttribute(scan_kernel, cudaFuncAttributeMaxDynamicSharedMemorySize, smem_scan);
    cudaFuncSetAttribute(fir_stats_kernel, cudaFuncAttributeMaxDynamicSharedMemorySize, smem_fir);
    cudaFuncSetAttribute(tgemm_kernel, cudaFuncAttributeMaxDynamicSharedMemorySize, SMEM_GEMM);
    cudaFuncSetAttribute(tgemm_router_kernel, cudaFuncAttributeMaxDynamicSharedMemorySize, SMEM_GEMM);

    // ---- init + conversions ----
    zero_kernel<<<96, 256>>>(lgts, NTOK*12/4);
    f2bf_split_kernel<<<4096, 256>>>(x, xhi, xlo, 8192*1024/8);
    f2bf_pack_qkv_kernel<<<1600, 256>>>(Wq, Wk, Wv, Wb, Wid, wqkvhi, wqkvlo);
    f2bf_split_kernel<<<512, 256>>>(Wo, wohi, wolo, 1024*1024/8);
    f2bf_split_pad_kernel<<<1088, 256>>>(Wr1, w1hi, w1lo);

    dim3 blk(256);
    dim3 gqkv(25, 64);
    tgemm_kernel<<<gqkv, blk, SMEM_GEMM>>>(xhi, xlo, wqkvhi, wqkvlo, qkvlin, NTOK, 3200, 1024);
    beta_sid_kernel<<<128, 256>>>(qkvlin, bid, beta, sidb);
    conv_silu_kernel<<<3*NTOK*4, 256>>>(qkvlin, cq, ck, cv, qb, kb, vb);
    chunk_prep_kernel<<<1024, 256, smem_prep>>>(qb, kb, vb, beta, ub, wb, attn);
    scan_kernel<<<128, 512, smem_scan>>>(qb, kb, ub, wb, attn, dlt);
    dim3 gfir(NTOK/32, 4);
    fir_stats_kernel<<<gfir, 256, smem_fir>>>(vb, dlt, firS, firL, fsb, flb, sthi, stlo);
    dim3 g2(16, 64);
    tgemm_router_kernel<<<g2, blk, SMEM_GEMM>>>(xhi, xlo, sthi, stlo, w1hi, w1lo, br1, Wr2, lgts);
    softmax_router_kernel<<<32, 256>>>(lgts, br2, ltg, pb);
    mix_norm_kernel<<<NTOK, 256>>>(pb, fsb, flb, dlt, vb, sidb, aid, onw, omhi, omlo);
    dim3 g1(8, 64);
    tgemm_kernel<<<g1, blk, SMEM_GEMM>>>(omhi, omlo, wohi, wolo, out, NTOK, 1024, 1024);
}